// round 13
// baseline (speedup 1.0000x reference)
#include <cuda_runtime.h>
#include <cuda_bf16.h>
#include <math.h>
#include <cstdint>

#define NV      81920
#define NP      131072
#define NC      512
#define NM      1024
#define NPORIG  163840
#define NT      262144

// ---------------- scratch (static device globals; no allocations) -----------
__device__ __align__(16) __nv_bfloat16  d_featsbf[(size_t)NP * NC];  // bf16 normalized feats
__device__ __align__(16) __nv_bfloat16  d_Ebf[(size_t)NM * NC];      // bf16 caption embeds
__device__ float d_lse[NP];
__device__ int   d_ptom[NPORIG];
__device__ __align__(16) float d_g[(size_t)NM * NC];
__device__ float d_Lsum[NM];
__device__ float d_realn[NM];

// ---------------- helpers (arch-agnostic: ldmatrix + mma.sync + cp.async) ---
__device__ __forceinline__ uint32_t smem_u32(const void* p) {
    uint32_t a;
    asm("{ .reg .u64 t; cvta.to.shared.u64 t, %1; cvt.u32.u64 %0, t; }" : "=r"(a) : "l"(p));
    return a;
}
__device__ __forceinline__ void ldsm4(uint32_t* r, uint32_t addr) {
    asm volatile("ldmatrix.sync.aligned.m8n8.x4.shared.b16 {%0,%1,%2,%3}, [%4];"
                 : "=r"(r[0]), "=r"(r[1]), "=r"(r[2]), "=r"(r[3]) : "r"(addr));
}
__device__ __forceinline__ void mma16816(float* d, const uint32_t* a, uint32_t b0, uint32_t b1) {
    asm volatile("mma.sync.aligned.m16n8k16.row.col.f32.bf16.bf16.f32 "
                 "{%0,%1,%2,%3}, {%4,%5,%6,%7}, {%8,%9}, {%0,%1,%2,%3};"
                 : "+f"(d[0]), "+f"(d[1]), "+f"(d[2]), "+f"(d[3])
                 : "r"(a[0]), "r"(a[1]), "r"(a[2]), "r"(a[3]), "r"(b0), "r"(b1));
}
__device__ __forceinline__ void cp16(uint32_t dst, const void* src) {
    asm volatile("cp.async.cg.shared.global [%0], [%1], 16;" :: "r"(dst), "l"(src));
}
__device__ __forceinline__ void cp_commit() { asm volatile("cp.async.commit_group;"); }
__device__ __forceinline__ void cp_wait0()  { asm volatile("cp.async.wait_group 0;"); }

// ---------------- init ------------------------------------------------------
__global__ void k_init() {
    int i = blockIdx.x * blockDim.x + threadIdx.x;
    if (i < NPORIG) d_ptom[i] = -1;
}

// ptom[origin_idx[i]] = i, duplicates: largest i wins (XLA sequential scatter)
__global__ void k_scatter(const int* __restrict__ origin) {
    int i = blockIdx.x * blockDim.x + threadIdx.x;
    if (i < NP) atomicMax(&d_ptom[origin[i]], i);
}

// E -> bf16 (1 MB, stays L2-resident for the GEMM)
__global__ void k_prepE(const float* __restrict__ E) {
    int idx = blockIdx.x * blockDim.x + threadIdx.x;   // < NM*NC/4
    float4 v = reinterpret_cast<const float4*>(E)[idx];
    __nv_bfloat162 h0 = __float22bfloat162_rn(make_float2(v.x, v.y));
    __nv_bfloat162 h1 = __float22bfloat162_rn(make_float2(v.z, v.w));
    uint2 u;
    u.x = *reinterpret_cast<uint32_t*>(&h0);
    u.y = *reinterpret_cast<uint32_t*>(&h1);
    reinterpret_cast<uint2*>(d_Ebf)[idx] = u;
}

// ---------------- fused norm + lse GEMM: 64 rows x 1024 caps x 512 per CTA --
// 256 threads, 8 warps in a 2(M)x4(N) grid of 32x64 tiles, 2 CTAs/SM.
// N-chunk 256, K-chunk 32: each A fragment feeds 8 MMAs (was 4) -> smem
// ldsm traffic per warp-stage drops 8KB -> 6KB; HMMA pipe becomes sole binder.
#define A_STRIDE 520
#define A_BYTES  (64 * A_STRIDE * 2)     // 66560
#define KC       32
#define B_STRIDE 40
#define B_BYTES  (256 * B_STRIDE * 2)    // 20480
#define SMEM_MMA (A_BYTES + 2 * B_BYTES) // 107520

__device__ __forceinline__ void issue_B(uint32_t sB, int buf, int nc, int kc, int tid) {
    const __nv_bfloat16* bsrc = d_Ebf + (size_t)(nc * 256) * NC + kc * KC;
    uint32_t dbase = sB + buf * B_BYTES;
#pragma unroll
    for (int i = 0; i < 4; i++) {
        int idx = tid + i * 256;            // 1024 x 16B
        int row = idx >> 2, seg = idx & 3;
        cp16(dbase + (row * B_STRIDE + seg * 8) * 2, bsrc + (size_t)row * NC + seg * 8);
    }
}

__global__ void __launch_bounds__(256, 2)
k_gemm_lse_mma(const float* __restrict__ adapter, const int* __restrict__ v2p,
               const float* __restrict__ lscale) {
    extern __shared__ char smem[];
    __shared__ float srow[64];
    const uint32_t sA = smem_u32(smem);
    const uint32_t sB = sA + A_BYTES;
    const int tid = threadIdx.x, lane = tid & 31, wid = tid >> 5;
    const int warp_m = wid & 1, warp_n = wid >> 1;   // 2x4 warp grid, 32x64 each
    const int p0 = blockIdx.x * 64;

    if (tid < 64) srow[tid] = 0.f;

    // B(0,0) in flight while we do the fused norm prolog
    issue_B(sB, 0, 0, 0, tid);
    cp_commit();

    // fused gather + L2-normalize: warp per point, 8 points per warp
    for (int r = wid; r < 64; r += 8) {
        const int p = p0 + r;
        const float4* src = reinterpret_cast<const float4*>(adapter + (size_t)v2p[p] * NC);
        float4 v[4];
        float ss = 0.f;
#pragma unroll
        for (int i = 0; i < 4; i++) {
            v[i] = src[lane + 32 * i];
            ss += v[i].x * v[i].x + v[i].y * v[i].y + v[i].z * v[i].z + v[i].w * v[i].w;
        }
#pragma unroll
        for (int o = 16; o > 0; o >>= 1) ss += __shfl_xor_sync(0xffffffffu, ss, o);
        float scale = 1.f / fmaxf(sqrtf(ss), 1e-12f);
        uint2* gdst = reinterpret_cast<uint2*>(d_featsbf + (size_t)p * NC);
        char*  sdst = smem + r * (A_STRIDE * 2);
#pragma unroll
        for (int i = 0; i < 4; i++) {
            float4 w = v[i];
            w.x *= scale; w.y *= scale; w.z *= scale; w.w *= scale;
            __nv_bfloat162 h0 = __float22bfloat162_rn(make_float2(w.x, w.y));
            __nv_bfloat162 h1 = __float22bfloat162_rn(make_float2(w.z, w.w));
            uint2 u;
            u.x = *reinterpret_cast<uint32_t*>(&h0);
            u.y = *reinterpret_cast<uint32_t*>(&h1);
            gdst[lane + 32 * i] = u;                                  // for k_segacc
            *reinterpret_cast<uint2*>(sdst + (lane + 32 * i) * 8) = u; // smem A
        }
    }
    __syncthreads();   // A tile ready for all warps

    const float s = expf(lscale[0]);

    // ldmatrix per-lane byte offsets
    const uint32_t aoff = ((warp_m * 32 + (lane & 15)) * A_STRIDE + ((lane >> 4) << 3)) * 2;
    const uint32_t boff = ((warp_n * 64 + (lane & 7) + ((lane >> 4) << 3)) * B_STRIDE
                          + ((lane >> 3) & 1) * 8) * 2;

    float t[4] = {0.f, 0.f, 0.f, 0.f};   // per-thread row exp-sums (rows fixed across nc)

    for (int nc = 0; nc < 4; nc++) {
        float acc[2][8][4];
#pragma unroll
        for (int i = 0; i < 2; i++)
#pragma unroll
            for (int j = 0; j < 8; j++)
#pragma unroll
                for (int k = 0; k < 4; k++) acc[i][j][k] = 0.f;

        for (int kc = 0; kc < 16; kc++) {
            cp_wait0();
            __syncthreads();   // stage (nc,kc) visible; prior buffer reads done
            // prefetch next stage into the other buffer (overlaps compute below)
            if (kc < 15)       { issue_B(sB, (kc + 1) & 1, nc, kc + 1, tid); cp_commit(); }
            else if (nc < 3)   { issue_B(sB, 0, nc + 1, 0, tid);             cp_commit(); }

            const uint32_t abase = sA + aoff + kc * (KC * 2);
            const uint32_t bbase = sB + (kc & 1) * B_BYTES + boff;
#pragma unroll
            for (int kk = 0; kk < 2; kk++) {
                uint32_t a0[4], a1[4];
                ldsm4(a0, abase + kk * 32);
                ldsm4(a1, abase + kk * 32 + 16 * A_STRIDE * 2);
#pragma unroll
                for (int nq = 0; nq < 4; nq++) {
                    uint32_t b[4];
                    ldsm4(b, bbase + kk * 32 + nq * 16 * B_STRIDE * 2);
                    mma16816(acc[0][2 * nq],     a0, b[0], b[1]);
                    mma16816(acc[0][2 * nq + 1], a0, b[2], b[3]);
                    mma16816(acc[1][2 * nq],     a1, b[0], b[1]);
                    mma16816(acc[1][2 * nq + 1], a1, b[2], b[3]);
                }
            }
        }
        // epilogue: exp-sum this 256-caption chunk into register totals
#pragma unroll
        for (int mt = 0; mt < 2; mt++)
#pragma unroll
            for (int nt = 0; nt < 8; nt++) {
                t[mt * 2 + 0] += __expf(s * acc[mt][nt][0]) + __expf(s * acc[mt][nt][1]);
                t[mt * 2 + 1] += __expf(s * acc[mt][nt][2]) + __expf(s * acc[mt][nt][3]);
            }
    }

    // reduce across the 4 lanes sharing each row, then across warp_n via smem
#pragma unroll
    for (int i = 0; i < 4; i++) {
        t[i] += __shfl_xor_sync(0xffffffffu, t[i], 1);
        t[i] += __shfl_xor_sync(0xffffffffu, t[i], 2);
    }
    if ((lane & 3) == 0) {
#pragma unroll
        for (int i = 0; i < 4; i++) {
            int r = warp_m * 32 + (i >> 1) * 16 + (i & 1) * 8 + (lane >> 2);
            atomicAdd(&srow[r], t[i]);
        }
    }
    __syncthreads();
    if (tid < 64) d_lse[p0 + tid] = logf(srow[tid]);
}

// ---------------- per-caption segmented accumulation (seg_idx is sorted) ----
// gathers bf16 rows (half the traffic), accumulates fp32
__device__ __forceinline__ int lb(const int* a, int n, int key) {
    int lo = 0, hi = n;
    while (lo < hi) { int mid = (lo + hi) >> 1; if (a[mid] < key) lo = mid + 1; else hi = mid; }
    return lo;
}

__global__ void k_segacc(const int* __restrict__ ctpm, const int* __restrict__ seg) {
    const int n = blockIdx.x;
    const int tid = threadIdx.x;  // 256: thread owns cols 2*tid, 2*tid+1
    const int start = lb(seg, NT, n);
    const int end   = lb(seg, NT, n + 1);

    float ax = 0, ay = 0, bx = 0, by = 0, cx = 0, cy = 0, ex = 0, ey = 0;
    int t = start;
    for (; t + 4 <= end; t += 4) {
        int p_[4];
#pragma unroll
        for (int u = 0; u < 4; u++) {
            int gi = d_ptom[ctpm[t + u]];
            p_[u] = (gi < 0) ? (NP - 1) : gi;   // torch negative-index wrap
        }
        const uint32_t* r0 = reinterpret_cast<const uint32_t*>(d_featsbf + (size_t)p_[0] * NC);
        const uint32_t* r1 = reinterpret_cast<const uint32_t*>(d_featsbf + (size_t)p_[1] * NC);
        const uint32_t* r2 = reinterpret_cast<const uint32_t*>(d_featsbf + (size_t)p_[2] * NC);
        const uint32_t* r3 = reinterpret_cast<const uint32_t*>(d_featsbf + (size_t)p_[3] * NC);
        uint32_t u0 = r0[tid], u1 = r1[tid], u2 = r2[tid], u3 = r3[tid];
        float2 f0 = __bfloat1622float2(*reinterpret_cast<__nv_bfloat162*>(&u0));
        float2 f1 = __bfloat1622float2(*reinterpret_cast<__nv_bfloat162*>(&u1));
        float2 f2 = __bfloat1622float2(*reinterpret_cast<__nv_bfloat162*>(&u2));
        float2 f3 = __bfloat1622float2(*reinterpret_cast<__nv_bfloat162*>(&u3));
        ax += f0.x; ay += f0.y;
        bx += f1.x; by += f1.y;
        cx += f2.x; cy += f2.y;
        ex += f3.x; ey += f3.y;
    }
    for (; t < end; ++t) {
        int gi = d_ptom[ctpm[t]];
        int p = (gi < 0) ? (NP - 1) : gi;
        uint32_t u = reinterpret_cast<const uint32_t*>(d_featsbf + (size_t)p * NC)[tid];
        float2 f = __bfloat1622float2(*reinterpret_cast<__nv_bfloat162*>(&u));
        ax += f.x; ay += f.y;
    }
    reinterpret_cast<float2*>(d_g + (size_t)n * NC)[tid] =
        make_float2(ax + bx + cx + ex, ay + by + cy + ey);

    float lsum = 0.f; int vc = 0;
    for (int tt = start + tid; tt < end; tt += 256) {
        int gi = d_ptom[ctpm[tt]];
        int p = (gi < 0) ? (NP - 1) : gi;
        lsum += d_lse[p];
        vc   += (gi >= 0);
    }
    __shared__ float sf[256];
    __shared__ int   si[256];
    sf[tid] = lsum; si[tid] = vc;
    __syncthreads();
    for (int st = 128; st > 0; st >>= 1) {
        if (tid < st) { sf[tid] += sf[tid + st]; si[tid] += si[tid + st]; }
        __syncthreads();
    }
    if (tid == 0) { d_Lsum[n] = sf[0]; d_realn[n] = (float)si[0]; }
}

// ---------------- final small GEMM: pooled = (s*(g @ E^T) - L)/c  (fp32) ----
__launch_bounds__(256, 2)
__global__ void k_final(const float* __restrict__ E, const float* __restrict__ lscale,
                        float* __restrict__ out) {
    __shared__ __align__(16) float As[16][128];
    __shared__ __align__(16) float Bs[16][128];

    const int tid = threadIdx.x;
    const int r0g = blockIdx.y * 128;
    const int n0  = blockIdx.x * 128;
    const int tr = tid >> 4, tc = tid & 15;

    float acc[8][8];
#pragma unroll
    for (int i = 0; i < 8; i++)
#pragma unroll
        for (int j = 0; j < 8; j++) acc[i][j] = 0.f;

    for (int k0 = 0; k0 < NC; k0 += 16) {
#pragma unroll
        for (int i = 0; i < 2; i++) {
            int li  = tid * 2 + i;
            int row = li >> 2;
            int f4  = li & 3;
            float4 a = *reinterpret_cast<const float4*>(
                d_g + (size_t)(r0g + row) * NC + k0 + f4 * 4);
            As[f4 * 4 + 0][row] = a.x; As[f4 * 4 + 1][row] = a.y;
            As[f4 * 4 + 2][row] = a.z; As[f4 * 4 + 3][row] = a.w;
            float4 b = *reinterpret_cast<const float4*>(
                E + (size_t)(n0 + row) * NC + k0 + f4 * 4);
            Bs[f4 * 4 + 0][row] = b.x; Bs[f4 * 4 + 1][row] = b.y;
            Bs[f4 * 4 + 2][row] = b.z; Bs[f4 * 4 + 3][row] = b.w;
        }
        __syncthreads();
#pragma unroll
        for (int k = 0; k < 16; k++) {
            float4 a0 = *reinterpret_cast<const float4*>(&As[k][tr * 4]);
            float4 a1 = *reinterpret_cast<const float4*>(&As[k][64 + tr * 4]);
            float4 b0 = *reinterpret_cast<const float4*>(&Bs[k][tc * 4]);
            float4 b1 = *reinterpret_cast<const float4*>(&Bs[k][64 + tc * 4]);
            float ar[8] = {a0.x, a0.y, a0.z, a0.w, a1.x, a1.y, a1.z, a1.w};
            float br[8] = {b0.x, b0.y, b0.z, b0.w, b1.x, b1.y, b1.z, b1.w};
#pragma unroll
            for (int i = 0; i < 8; i++)
#pragma unroll
                for (int j = 0; j < 8; j++) acc[i][j] = fmaf(ar[i], br[j], acc[i][j]);
        }
        __syncthreads();
    }

    const float s = expf(lscale[0]);
#pragma unroll
    for (int i = 0; i < 8; i++) {
        int ri = (i < 4) ? (tr * 4 + i) : (64 + tr * 4 + (i - 4));
        int n = r0g + ri;
        float c = d_realn[n];
        float invc = (c > 0.f) ? (1.f / c) : 0.f;
        float L = d_Lsum[n];
#pragma unroll
        for (int j = 0; j < 8; j++) {
            int cj = (j < 4) ? (tc * 4 + j) : (64 + tc * 4 + (j - 4));
            int m = n0 + cj;
            out[(size_t)n * NM + m] = (s * acc[i][j] - L) * invc;
        }
    }
}

__global__ void k_tail(float* __restrict__ out, int out_size) {
    int n = blockIdx.x * blockDim.x + threadIdx.x;
    if (n >= NM) return;
    size_t base = (size_t)NM * NM;
    if (out_size >= (int)(base + NM))        out[base + n] = d_realn[n];
    if (out_size >= (int)(base + 2 * NM))    out[base + NM + n] = (d_realn[n] > 0.f) ? 1.f : 0.f;
}

// ---------------- launch ----------------------------------------------------
extern "C" void kernel_launch(void* const* d_in, const int* in_sizes, int n_in,
                              void* d_out, int out_size) {
    const float* adapter = (const float*)d_in[0];   // [V, C]
    const float* E       = (const float*)d_in[1];   // [M, C]
    const float* lscale  = (const float*)d_in[2];   // [1]
    const int*   v2p     = (const int*)d_in[3];     // [P]
    const int*   origin  = (const int*)d_in[4];     // [P]
    const int*   ctpm    = (const int*)d_in[5];     // [T]
    const int*   seg     = (const int*)d_in[6];     // [T] sorted
    float* out = (float*)d_out;

    static int smem_set = 0;
    if (!smem_set) {
        cudaFuncSetAttribute(k_gemm_lse_mma, cudaFuncAttributeMaxDynamicSharedMemorySize, SMEM_MMA);
        smem_set = 1;
    }

    k_init<<<(NPORIG + 255) / 256, 256>>>();
    k_scatter<<<NP / 256, 256>>>(origin);
    k_prepE<<<(NM * NC / 4) / 256, 256>>>(E);
    k_gemm_lse_mma<<<NP / 64, 256, SMEM_MMA>>>(adapter, v2p, lscale);
    k_segacc<<<NM, 256>>>(ctpm, seg);
    dim3 g2(NM / 128, NM / 128);
    k_final<<<g2, 256>>>(E, lscale, out);
    k_tail<<<(NM + 255) / 256, 256>>>(out, out_size);
}

// round 14
// speedup vs baseline: 1.0701x; 1.0701x over previous
#include <cuda_runtime.h>
#include <cuda_bf16.h>
#include <math.h>
#include <cstdint>

#define NV      81920
#define NP      131072
#define NC      512
#define NM      1024
#define NPORIG  163840
#define NT      262144

// ---------------- scratch (static device globals; no allocations) -----------
__device__ __align__(16) __nv_bfloat16  d_featsbf[(size_t)NP * NC];  // bf16 normalized feats
__device__ __align__(16) uint8_t        d_E8[(size_t)NM * NC];       // e4m3 caption embeds
__device__ float d_lse[NP];
__device__ int   d_ptom[NPORIG];
__device__ __align__(16) float d_g[(size_t)NM * NC];
__device__ float d_Lsum[NM];
__device__ float d_realn[NM];

// ---------------- helpers (base-ISA: ldmatrix + mma.sync + cp.async) --------
__device__ __forceinline__ uint32_t smem_u32(const void* p) {
    uint32_t a;
    asm("{ .reg .u64 t; cvta.to.shared.u64 t, %1; cvt.u32.u64 %0, t; }" : "=r"(a) : "l"(p));
    return a;
}
__device__ __forceinline__ void ldsm4(uint32_t* r, uint32_t addr) {
    asm volatile("ldmatrix.sync.aligned.m8n8.x4.shared.b16 {%0,%1,%2,%3}, [%4];"
                 : "=r"(r[0]), "=r"(r[1]), "=r"(r[2]), "=r"(r[3]) : "r"(addr));
}
// fp8 m16n8k32: base ISA since sm_89 (not an 'a'-gated feature)
__device__ __forceinline__ void mma16832(float* d, const uint32_t* a, uint32_t b0, uint32_t b1) {
    asm volatile("mma.sync.aligned.m16n8k32.row.col.f32.e4m3.e4m3.f32 "
                 "{%0,%1,%2,%3}, {%4,%5,%6,%7}, {%8,%9}, {%0,%1,%2,%3};"
                 : "+f"(d[0]), "+f"(d[1]), "+f"(d[2]), "+f"(d[3])
                 : "r"(a[0]), "r"(a[1]), "r"(a[2]), "r"(a[3]), "r"(b0), "r"(b1));
}
__device__ __forceinline__ uint32_t pack_e4m3x4(float x, float y, float z, float w) {
    uint16_t q0, q1;   // first src -> high byte
    asm("cvt.rn.satfinite.e4m3x2.f32 %0, %1, %2;" : "=h"(q0) : "f"(y), "f"(x));
    asm("cvt.rn.satfinite.e4m3x2.f32 %0, %1, %2;" : "=h"(q1) : "f"(w), "f"(z));
    return (uint32_t)q0 | ((uint32_t)q1 << 16);
}
__device__ __forceinline__ void cp16(uint32_t dst, const void* src) {
    asm volatile("cp.async.cg.shared.global [%0], [%1], 16;" :: "r"(dst), "l"(src));
}
__device__ __forceinline__ void cp_commit() { asm volatile("cp.async.commit_group;"); }
__device__ __forceinline__ void cp_wait0()  { asm volatile("cp.async.wait_group 0;"); }

// ---------------- init: ptom = -1  +  E -> e4m3 -----------------------------
__global__ void k_init(const float* __restrict__ E) {
    int i = blockIdx.x * blockDim.x + threadIdx.x;
    if (i < NPORIG) d_ptom[i] = -1;
    if (i < NM * NC / 4) {
        float4 v = reinterpret_cast<const float4*>(E)[i];
        reinterpret_cast<uint32_t*>(d_E8)[i] = pack_e4m3x4(v.x, v.y, v.z, v.w);
    }
}

// ptom[origin_idx[i]] = i, duplicates: largest i wins (XLA sequential scatter)
__global__ void k_scatter(const int* __restrict__ origin) {
    int i = blockIdx.x * blockDim.x + threadIdx.x;
    if (i < NP) atomicMax(&d_ptom[origin[i]], i);
}

// ---------------- fused norm + lse GEMM (fp8): 64 rows x 1024 caps x 512 ----
// 256 threads, 8 warps in 2(M)x4(N) grid of 32x32 tiles, 2 CTAs/SM.
// A: 64 x 512 e4m3 in smem (stride 528B); B: ping-pong 128 caps x 64 e4m3.
// fp8-k32 fragments are byte-identical to bf16-k16 fragments -> same ldmatrix
// addressing as the proven R11 kernel, half the smem traffic + HMMA issues.
#define A_STRIDE 528
#define A_BYTES  (64 * A_STRIDE)         // 33792
#define KC       64
#define B_STRIDE 80
#define B_BYTES  (128 * B_STRIDE)        // 10240
#define SMEM_MMA (A_BYTES + 2 * B_BYTES) // 54272

__device__ __forceinline__ void issue_B(uint32_t sB, int buf, int nc, int kc, int tid) {
    const uint8_t* bsrc = d_E8 + (size_t)(nc * 128) * NC + kc * KC;
    uint32_t dbase = sB + buf * B_BYTES;
#pragma unroll
    for (int i = 0; i < 2; i++) {
        int idx = tid + i * 256;            // 512 x 16B
        int row = idx >> 2, seg = idx & 3;
        cp16(dbase + row * B_STRIDE + seg * 16, bsrc + (size_t)row * NC + seg * 16);
    }
}

__global__ void __launch_bounds__(256, 2)
k_gemm_lse_mma(const float* __restrict__ adapter, const int* __restrict__ v2p,
               const float* __restrict__ lscale) {
    extern __shared__ char smem[];
    __shared__ float srow[64];
    const uint32_t sA = smem_u32(smem);
    const uint32_t sB = sA + A_BYTES;
    const int tid = threadIdx.x, lane = tid & 31, wid = tid >> 5;
    const int warp_m = wid & 1, warp_n = wid >> 1;   // 2x4 warp grid, 32x32 each
    const int p0 = blockIdx.x * 64;

    if (tid < 64) srow[tid] = 0.f;

    // B(0,0) in flight while we do the fused norm prolog
    issue_B(sB, 0, 0, 0, tid);
    cp_commit();

    // fused gather + L2-normalize: warp per point; bf16 to gmem, e4m3 to smem A
    for (int r = wid; r < 64; r += 8) {
        const int p = p0 + r;
        const float4* src = reinterpret_cast<const float4*>(adapter + (size_t)v2p[p] * NC);
        float4 v[4];
        float ss = 0.f;
#pragma unroll
        for (int i = 0; i < 4; i++) {
            v[i] = src[lane + 32 * i];
            ss += v[i].x * v[i].x + v[i].y * v[i].y + v[i].z * v[i].z + v[i].w * v[i].w;
        }
#pragma unroll
        for (int o = 16; o > 0; o >>= 1) ss += __shfl_xor_sync(0xffffffffu, ss, o);
        float scale = 1.f / fmaxf(sqrtf(ss), 1e-12f);
        uint2* gdst = reinterpret_cast<uint2*>(d_featsbf + (size_t)p * NC);
        char*  sdst = smem + r * A_STRIDE;
#pragma unroll
        for (int i = 0; i < 4; i++) {
            float4 w = v[i];
            w.x *= scale; w.y *= scale; w.z *= scale; w.w *= scale;
            __nv_bfloat162 h0 = __float22bfloat162_rn(make_float2(w.x, w.y));
            __nv_bfloat162 h1 = __float22bfloat162_rn(make_float2(w.z, w.w));
            uint2 u;
            u.x = *reinterpret_cast<uint32_t*>(&h0);
            u.y = *reinterpret_cast<uint32_t*>(&h1);
            gdst[lane + 32 * i] = u;                                   // for k_segacc
            *reinterpret_cast<uint32_t*>(sdst + (lane + 32 * i) * 4) =
                pack_e4m3x4(w.x, w.y, w.z, w.w);                       // smem A (fp8)
        }
    }
    __syncthreads();   // A tile ready for all warps

    const float s = expf(lscale[0]);

    // ldmatrix per-lane byte offsets (byte-identical mapping to bf16-k16 case)
    const uint32_t aoff = (warp_m * 32 + (lane & 15)) * A_STRIDE + ((lane >> 4) << 4);
    const uint32_t boff = (warp_n * 32 + (lane & 7) + ((lane >> 4) << 3)) * B_STRIDE
                          + (((lane >> 3) & 1) << 4);

    float t[4] = {0.f, 0.f, 0.f, 0.f};   // per-thread row exp-sums (rows fixed across nc)

    for (int nc = 0; nc < 8; nc++) {
        float acc[2][4][4];
#pragma unroll
        for (int i = 0; i < 2; i++)
#pragma unroll
            for (int j = 0; j < 4; j++)
#pragma unroll
                for (int k = 0; k < 4; k++) acc[i][j][k] = 0.f;

        for (int kc = 0; kc < 8; kc++) {
            cp_wait0();
            __syncthreads();   // stage (nc,kc) visible; prior buffer reads done
            // prefetch next stage into the other buffer (overlaps compute below)
            if (kc < 7)        { issue_B(sB, (kc + 1) & 1, nc, kc + 1, tid); cp_commit(); }
            else if (nc < 7)   { issue_B(sB, 0, nc + 1, 0, tid);             cp_commit(); }

            const uint32_t abase = sA + aoff + kc * KC;          // 64 bytes of K per stage
            const uint32_t bbase = sB + (kc & 1) * B_BYTES + boff;
#pragma unroll
            for (int kk = 0; kk < 2; kk++) {                     // k32 per mma
                uint32_t a0[4], a1[4];
                ldsm4(a0, abase + kk * 32);
                ldsm4(a1, abase + kk * 32 + 16 * A_STRIDE);
#pragma unroll
                for (int np = 0; np < 2; np++) {
                    uint32_t b[4];
                    ldsm4(b, bbase + kk * 32 + np * 16 * B_STRIDE);
                    mma16832(acc[0][2 * np],     a0, b[0], b[1]);
                    mma16832(acc[0][2 * np + 1], a0, b[2], b[3]);
                    mma16832(acc[1][2 * np],     a1, b[0], b[1]);
                    mma16832(acc[1][2 * np + 1], a1, b[2], b[3]);
                }
            }
        }
        // epilogue: exp-sum this 128-caption chunk into register totals
#pragma unroll
        for (int mt = 0; mt < 2; mt++)
#pragma unroll
            for (int nt = 0; nt < 4; nt++) {
                t[mt * 2 + 0] += __expf(s * acc[mt][nt][0]) + __expf(s * acc[mt][nt][1]);
                t[mt * 2 + 1] += __expf(s * acc[mt][nt][2]) + __expf(s * acc[mt][nt][3]);
            }
    }

    // reduce across the 4 lanes sharing each row, then across warp_n via smem
#pragma unroll
    for (int i = 0; i < 4; i++) {
        t[i] += __shfl_xor_sync(0xffffffffu, t[i], 1);
        t[i] += __shfl_xor_sync(0xffffffffu, t[i], 2);
    }
    if ((lane & 3) == 0) {
#pragma unroll
        for (int i = 0; i < 4; i++) {
            int r = warp_m * 32 + (i >> 1) * 16 + (i & 1) * 8 + (lane >> 2);
            atomicAdd(&srow[r], t[i]);
        }
    }
    __syncthreads();
    if (tid < 64) d_lse[p0 + tid] = logf(srow[tid]);
}

// ---------------- per-caption segmented accumulation (seg_idx is sorted) ----
// gathers bf16 rows, accumulates fp32
__device__ __forceinline__ int lb(const int* a, int n, int key) {
    int lo = 0, hi = n;
    while (lo < hi) { int mid = (lo + hi) >> 1; if (a[mid] < key) lo = mid + 1; else hi = mid; }
    return lo;
}

__global__ void k_segacc(const int* __restrict__ ctpm, const int* __restrict__ seg) {
    const int n = blockIdx.x;
    const int tid = threadIdx.x;  // 256: thread owns cols 2*tid, 2*tid+1
    const int start = lb(seg, NT, n);
    const int end   = lb(seg, NT, n + 1);

    float ax = 0, ay = 0, bx = 0, by = 0, cx = 0, cy = 0, ex = 0, ey = 0;
    int t = start;
    for (; t + 4 <= end; t += 4) {
        int p_[4];
#pragma unroll
        for (int u = 0; u < 4; u++) {
            int gi = d_ptom[ctpm[t + u]];
            p_[u] = (gi < 0) ? (NP - 1) : gi;   // torch negative-index wrap
        }
        const uint32_t* r0 = reinterpret_cast<const uint32_t*>(d_featsbf + (size_t)p_[0] * NC);
        const uint32_t* r1 = reinterpret_cast<const uint32_t*>(d_featsbf + (size_t)p_[1] * NC);
        const uint32_t* r2 = reinterpret_cast<const uint32_t*>(d_featsbf + (size_t)p_[2] * NC);
        const uint32_t* r3 = reinterpret_cast<const uint32_t*>(d_featsbf + (size_t)p_[3] * NC);
        uint32_t u0 = r0[tid], u1 = r1[tid], u2 = r2[tid], u3 = r3[tid];
        float2 f0 = __bfloat1622float2(*reinterpret_cast<__nv_bfloat162*>(&u0));
        float2 f1 = __bfloat1622float2(*reinterpret_cast<__nv_bfloat162*>(&u1));
        float2 f2 = __bfloat1622float2(*reinterpret_cast<__nv_bfloat162*>(&u2));
        float2 f3 = __bfloat1622float2(*reinterpret_cast<__nv_bfloat162*>(&u3));
        ax += f0.x; ay += f0.y;
        bx += f1.x; by += f1.y;
        cx += f2.x; cy += f2.y;
        ex += f3.x; ey += f3.y;
    }
    for (; t < end; ++t) {
        int gi = d_ptom[ctpm[t]];
        int p = (gi < 0) ? (NP - 1) : gi;
        uint32_t u = reinterpret_cast<const uint32_t*>(d_featsbf + (size_t)p * NC)[tid];
        float2 f = __bfloat1622float2(*reinterpret_cast<__nv_bfloat162*>(&u));
        ax += f.x; ay += f.y;
    }
    reinterpret_cast<float2*>(d_g + (size_t)n * NC)[tid] =
        make_float2(ax + bx + cx + ex, ay + by + cy + ey);

    float lsum = 0.f; int vc = 0;
    for (int tt = start + tid; tt < end; tt += 256) {
        int gi = d_ptom[ctpm[tt]];
        int p = (gi < 0) ? (NP - 1) : gi;
        lsum += d_lse[p];
        vc   += (gi >= 0);
    }
    __shared__ float sf[256];
    __shared__ int   si[256];
    sf[tid] = lsum; si[tid] = vc;
    __syncthreads();
    for (int st = 128; st > 0; st >>= 1) {
        if (tid < st) { sf[tid] += sf[tid + st]; si[tid] += si[tid + st]; }
        __syncthreads();
    }
    if (tid == 0) { d_Lsum[n] = sf[0]; d_realn[n] = (float)si[0]; }
}

// ---------------- final small GEMM: pooled = (s*(g @ E^T) - L)/c  (fp32) ----
__launch_bounds__(256, 2)
__global__ void k_final(const float* __restrict__ E, const float* __restrict__ lscale,
                        float* __restrict__ out) {
    __shared__ __align__(16) float As[16][128];
    __shared__ __align__(16) float Bs[16][128];

    const int tid = threadIdx.x;
    const int r0g = blockIdx.y * 128;
    const int n0  = blockIdx.x * 128;
    const int tr = tid >> 4, tc = tid & 15;

    float acc[8][8];
#pragma unroll
    for (int i = 0; i < 8; i++)
#pragma unroll
        for (int j = 0; j < 8; j++) acc[i][j] = 0.f;

    for (int k0 = 0; k0 < NC; k0 += 16) {
#pragma unroll
        for (int i = 0; i < 2; i++) {
            int li  = tid * 2 + i;
            int row = li >> 2;
            int f4  = li & 3;
            float4 a = *reinterpret_cast<const float4*>(
                d_g + (size_t)(r0g + row) * NC + k0 + f4 * 4);
            As[f4 * 4 + 0][row] = a.x; As[f4 * 4 + 1][row] = a.y;
            As[f4 * 4 + 2][row] = a.z; As[f4 * 4 + 3][row] = a.w;
            float4 b = *reinterpret_cast<const float4*>(
                E + (size_t)(n0 + row) * NC + k0 + f4 * 4);
            Bs[f4 * 4 + 0][row] = b.x; Bs[f4 * 4 + 1][row] = b.y;
            Bs[f4 * 4 + 2][row] = b.z; Bs[f4 * 4 + 3][row] = b.w;
        }
        __syncthreads();
#pragma unroll
        for (int k = 0; k < 16; k++) {
            float4 a0 = *reinterpret_cast<const float4*>(&As[k][tr * 4]);
            float4 a1 = *reinterpret_cast<const float4*>(&As[k][64 + tr * 4]);
            float4 b0 = *reinterpret_cast<const float4*>(&Bs[k][tc * 4]);
            float4 b1 = *reinterpret_cast<const float4*>(&Bs[k][64 + tc * 4]);
            float ar[8] = {a0.x, a0.y, a0.z, a0.w, a1.x, a1.y, a1.z, a1.w};
            float br[8] = {b0.x, b0.y, b0.z, b0.w, b1.x, b1.y, b1.z, b1.w};
#pragma unroll
            for (int i = 0; i < 8; i++)
#pragma unroll
                for (int j = 0; j < 8; j++) acc[i][j] = fmaf(ar[i], br[j], acc[i][j]);
        }
        __syncthreads();
    }

    const float s = expf(lscale[0]);
#pragma unroll
    for (int i = 0; i < 8; i++) {
        int ri = (i < 4) ? (tr * 4 + i) : (64 + tr * 4 + (i - 4));
        int n = r0g + ri;
        float c = d_realn[n];
        float invc = (c > 0.f) ? (1.f / c) : 0.f;
        float L = d_Lsum[n];
#pragma unroll
        for (int j = 0; j < 8; j++) {
            int cj = (j < 4) ? (tc * 4 + j) : (64 + tc * 4 + (j - 4));
            int m = n0 + cj;
            out[(size_t)n * NM + m] = (s * acc[i][j] - L) * invc;
        }
    }
}

__global__ void k_tail(float* __restrict__ out, int out_size) {
    int n = blockIdx.x * blockDim.x + threadIdx.x;
    if (n >= NM) return;
    size_t base = (size_t)NM * NM;
    if (out_size >= (int)(base + NM))        out[base + n] = d_realn[n];
    if (out_size >= (int)(base + 2 * NM))    out[base + NM + n] = (d_realn[n] > 0.f) ? 1.f : 0.f;
}

// ---------------- launch ----------------------------------------------------
extern "C" void kernel_launch(void* const* d_in, const int* in_sizes, int n_in,
                              void* d_out, int out_size) {
    const float* adapter = (const float*)d_in[0];   // [V, C]
    const float* E       = (const float*)d_in[1];   // [M, C]
    const float* lscale  = (const float*)d_in[2];   // [1]
    const int*   v2p     = (const int*)d_in[3];     // [P]
    const int*   origin  = (const int*)d_in[4];     // [P]
    const int*   ctpm    = (const int*)d_in[5];     // [T]
    const int*   seg     = (const int*)d_in[6];     // [T] sorted
    float* out = (float*)d_out;

    static int smem_set = 0;
    if (!smem_set) {
        cudaFuncSetAttribute(k_gemm_lse_mma, cudaFuncAttributeMaxDynamicSharedMemorySize, SMEM_MMA);
        smem_set = 1;
    }

    k_init<<<(NPORIG + 255) / 256, 256>>>(E);
    k_scatter<<<NP / 256, 256>>>(origin);
    k_gemm_lse_mma<<<NP / 64, 256, SMEM_MMA>>>(adapter, v2p, lscale);
    k_segacc<<<NM, 256>>>(ctpm, seg);
    dim3 g2(NM / 128, NM / 128);
    k_final<<<g2, 256>>>(E, lscale, out);
    k_tail<<<(NM + 255) / 256, 256>>>(out, out_size);
}

// round 16
// speedup vs baseline: 1.1740x; 1.0971x over previous
#include <cuda_runtime.h>
#include <cuda_bf16.h>
#include <math.h>
#include <cstdint>

#define NV      81920
#define NP      131072
#define NC      512
#define NM      1024
#define NPORIG  163840
#define NT      262144

// ---------------- scratch (static device globals; no allocations) -----------
__device__ __align__(16) __nv_bfloat16  d_featsbf[(size_t)NP * NC];  // bf16 normalized feats
__device__ __align__(16) __nv_bfloat16  d_Ebf[(size_t)NM * NC];      // bf16 caption embeds
__device__ float d_lse[NP];
__device__ int   d_ptom[NPORIG];
__device__ int   d_segstart[NM + 1];
__device__ __align__(16) float d_g[(size_t)NM * NC];
__device__ float d_Lsum[NM];
__device__ float d_realn[NM];

// ---------------- helpers (arch-agnostic: ldmatrix + mma.sync + cp.async) ---
__device__ __forceinline__ uint32_t smem_u32(const void* p) {
    uint32_t a;
    asm("{ .reg .u64 t; cvta.to.shared.u64 t, %1; cvt.u32.u64 %0, t; }" : "=r"(a) : "l"(p));
    return a;
}
__device__ __forceinline__ void ldsm4(uint32_t* r, uint32_t addr) {
    asm volatile("ldmatrix.sync.aligned.m8n8.x4.shared.b16 {%0,%1,%2,%3}, [%4];"
                 : "=r"(r[0]), "=r"(r[1]), "=r"(r[2]), "=r"(r[3]) : "r"(addr));
}
__device__ __forceinline__ void mma16816(float* d, const uint32_t* a, uint32_t b0, uint32_t b1) {
    asm volatile("mma.sync.aligned.m16n8k16.row.col.f32.bf16.bf16.f32 "
                 "{%0,%1,%2,%3}, {%4,%5,%6,%7}, {%8,%9}, {%0,%1,%2,%3};"
                 : "+f"(d[0]), "+f"(d[1]), "+f"(d[2]), "+f"(d[3])
                 : "r"(a[0]), "r"(a[1]), "r"(a[2]), "r"(a[3]), "r"(b0), "r"(b1));
}
__device__ __forceinline__ void cp16(uint32_t dst, const void* src) {
    asm volatile("cp.async.cg.shared.global [%0], [%1], 16;" :: "r"(dst), "l"(src));
}
__device__ __forceinline__ void cp_commit() { asm volatile("cp.async.commit_group;"); }
__device__ __forceinline__ void cp_wait0()  { asm volatile("cp.async.wait_group 0;"); }

__device__ __forceinline__ int lb(const int* a, int n, int key) {
    int lo = 0, hi = n;
    while (lo < hi) { int mid = (lo + hi) >> 1; if (a[mid] < key) lo = mid + 1; else hi = mid; }
    return lo;
}

// ---------------- init (side stream): ptom = -1 + segment starts ------------
__global__ void k_init(const int* __restrict__ seg) {
    int i = blockIdx.x * blockDim.x + threadIdx.x;
    if (i < NPORIG) d_ptom[i] = -1;
    if (i <= NM)    d_segstart[i] = lb(seg, NT, i);
}

// ptom[origin_idx[i]] = i, duplicates: largest i wins (XLA sequential scatter)
__global__ void k_scatter(const int* __restrict__ origin) {
    int i = blockIdx.x * blockDim.x + threadIdx.x;
    if (i < NP) atomicMax(&d_ptom[origin[i]], i);
}

// E -> bf16 (main stream; GEMM input, stays L2-resident)
__global__ void k_prepE(const float* __restrict__ E) {
    int idx = blockIdx.x * blockDim.x + threadIdx.x;   // < NM*NC/4
    float4 v = reinterpret_cast<const float4*>(E)[idx];
    __nv_bfloat162 h0 = __float22bfloat162_rn(make_float2(v.x, v.y));
    __nv_bfloat162 h1 = __float22bfloat162_rn(make_float2(v.z, v.w));
    uint2 u;
    u.x = *reinterpret_cast<uint32_t*>(&h0);
    u.y = *reinterpret_cast<uint32_t*>(&h1);
    reinterpret_cast<uint2*>(d_Ebf)[idx] = u;
}

// ---------------- fused norm + lse GEMM: 64 rows x 1024 caps x 512 per CTA --
// (R11 kernel verbatim: 256 threads, 2x4 warp grid of 32x32, 2 CTAs/SM)
#define A_STRIDE 520
#define A_BYTES  (64 * A_STRIDE * 2)     // 66560
#define KC       64
#define B_STRIDE 72
#define B_BYTES  (128 * B_STRIDE * 2)    // 18432
#define SMEM_MMA (A_BYTES + 2 * B_BYTES) // 103424

__device__ __forceinline__ void issue_B(uint32_t sB, int buf, int nc, int kc, int tid) {
    const __nv_bfloat16* bsrc = d_Ebf + (size_t)(nc * 128) * NC + kc * KC;
    uint32_t dbase = sB + buf * B_BYTES;
#pragma unroll
    for (int i = 0; i < 4; i++) {
        int idx = tid + i * 256;            // 1024 x 16B
        int row = idx >> 3, seg = idx & 7;
        cp16(dbase + (row * B_STRIDE + seg * 8) * 2, bsrc + (size_t)row * NC + seg * 8);
    }
}

__global__ void __launch_bounds__(256, 2)
k_gemm_lse_mma(const float* __restrict__ adapter, const int* __restrict__ v2p,
               const float* __restrict__ lscale) {
    extern __shared__ char smem[];
    __shared__ float srow[64];
    const uint32_t sA = smem_u32(smem);
    const uint32_t sB = sA + A_BYTES;
    const int tid = threadIdx.x, lane = tid & 31, wid = tid >> 5;
    const int warp_m = wid & 1, warp_n = wid >> 1;   // 2x4 warp grid, 32x32 each
    const int p0 = blockIdx.x * 64;

    if (tid < 64) srow[tid] = 0.f;

    // B(0,0) in flight while we do the fused norm prolog
    issue_B(sB, 0, 0, 0, tid);
    cp_commit();

    // fused gather + L2-normalize: warp per point, 8 points per warp
    for (int r = wid; r < 64; r += 8) {
        const int p = p0 + r;
        const float4* src = reinterpret_cast<const float4*>(adapter + (size_t)v2p[p] * NC);
        float4 v[4];
        float ss = 0.f;
#pragma unroll
        for (int i = 0; i < 4; i++) {
            v[i] = src[lane + 32 * i];
            ss += v[i].x * v[i].x + v[i].y * v[i].y + v[i].z * v[i].z + v[i].w * v[i].w;
        }
#pragma unroll
        for (int o = 16; o > 0; o >>= 1) ss += __shfl_xor_sync(0xffffffffu, ss, o);
        float scale = 1.f / fmaxf(sqrtf(ss), 1e-12f);
        uint2* gdst = reinterpret_cast<uint2*>(d_featsbf + (size_t)p * NC);
        char*  sdst = smem + r * (A_STRIDE * 2);
#pragma unroll
        for (int i = 0; i < 4; i++) {
            float4 w = v[i];
            w.x *= scale; w.y *= scale; w.z *= scale; w.w *= scale;
            __nv_bfloat162 h0 = __float22bfloat162_rn(make_float2(w.x, w.y));
            __nv_bfloat162 h1 = __float22bfloat162_rn(make_float2(w.z, w.w));
            uint2 u;
            u.x = *reinterpret_cast<uint32_t*>(&h0);
            u.y = *reinterpret_cast<uint32_t*>(&h1);
            gdst[lane + 32 * i] = u;                                  // for k_segacc
            *reinterpret_cast<uint2*>(sdst + (lane + 32 * i) * 8) = u; // smem A
        }
    }
    __syncthreads();   // A tile ready for all warps

    const float s = expf(lscale[0]);

    // ldmatrix per-lane byte offsets
    const uint32_t aoff = ((warp_m * 32 + (lane & 15)) * A_STRIDE + ((lane >> 4) << 3)) * 2;
    const uint32_t boff = ((warp_n * 32 + (lane & 7) + ((lane >> 4) << 3)) * B_STRIDE
                          + ((lane >> 3) & 1) * 8) * 2;

    float t[4] = {0.f, 0.f, 0.f, 0.f};   // per-thread row exp-sums (rows fixed across nc)

    for (int nc = 0; nc < 8; nc++) {
        float acc[2][4][4];
#pragma unroll
        for (int i = 0; i < 2; i++)
#pragma unroll
            for (int j = 0; j < 4; j++)
#pragma unroll
                for (int k = 0; k < 4; k++) acc[i][j][k] = 0.f;

        for (int kc = 0; kc < 8; kc++) {
            cp_wait0();
            __syncthreads();   // stage (nc,kc) visible; prior buffer reads done
            // prefetch next stage into the other buffer (overlaps compute below)
            if (kc < 7)        { issue_B(sB, (kc + 1) & 1, nc, kc + 1, tid); cp_commit(); }
            else if (nc < 7)   { issue_B(sB, 0, nc + 1, 0, tid);             cp_commit(); }

            const uint32_t abase = sA + aoff + kc * (KC * 2);
            const uint32_t bbase = sB + (kc & 1) * B_BYTES + boff;
#pragma unroll
            for (int kk = 0; kk < 4; kk++) {
                uint32_t a0[4], a1[4];
                ldsm4(a0, abase + kk * 32);
                ldsm4(a1, abase + kk * 32 + 16 * A_STRIDE * 2);
#pragma unroll
                for (int np = 0; np < 2; np++) {
                    uint32_t b[4];
                    ldsm4(b, bbase + kk * 32 + np * 16 * B_STRIDE * 2);
                    mma16816(acc[0][2 * np],     a0, b[0], b[1]);
                    mma16816(acc[0][2 * np + 1], a0, b[2], b[3]);
                    mma16816(acc[1][2 * np],     a1, b[0], b[1]);
                    mma16816(acc[1][2 * np + 1], a1, b[2], b[3]);
                }
            }
        }
        // epilogue: exp-sum this 128-caption chunk into register totals
#pragma unroll
        for (int mt = 0; mt < 2; mt++)
#pragma unroll
            for (int nt = 0; nt < 4; nt++) {
                t[mt * 2 + 0] += __expf(s * acc[mt][nt][0]) + __expf(s * acc[mt][nt][1]);
                t[mt * 2 + 1] += __expf(s * acc[mt][nt][2]) + __expf(s * acc[mt][nt][3]);
            }
    }

    // reduce across the 4 lanes sharing each row, then across warp_n via smem
#pragma unroll
    for (int i = 0; i < 4; i++) {
        t[i] += __shfl_xor_sync(0xffffffffu, t[i], 1);
        t[i] += __shfl_xor_sync(0xffffffffu, t[i], 2);
    }
    if ((lane & 3) == 0) {
#pragma unroll
        for (int i = 0; i < 4; i++) {
            int r = warp_m * 32 + (i >> 1) * 16 + (i & 1) * 8 + (lane >> 2);
            atomicAdd(&srow[r], t[i]);
        }
    }
    __syncthreads();
    if (tid < 64) d_lse[p0 + tid] = logf(srow[tid]);
}

// ---------------- per-caption segmented accumulation (seg_idx is sorted) ----
// phase 1: resolve indices once into smem (kills 256x-redundant LDG chains),
// fused with lse/count; phase 2: bf16 row gather via 1 broadcast LDS per t.
// tail outputs merged in.
__global__ void k_segacc(const int* __restrict__ ctpm,
                         float* __restrict__ out, int out_size) {
    const int n = blockIdx.x;
    const int tid = threadIdx.x;  // 256: thread owns cols 2*tid, 2*tid+1
    const int start = d_segstart[n];
    const int len   = d_segstart[n + 1] - start;

    __shared__ int   sp[1024];
    __shared__ float sf[256];
    __shared__ int   si[256];

    float lsum = 0.f; int vc = 0;
    for (int i = tid; i < len; i += 256) {
        int gi = d_ptom[ctpm[start + i]];
        int p = (gi < 0) ? (NP - 1) : gi;   // torch negative-index wrap
        if (i < 1024) sp[i] = p;
        lsum += d_lse[p];
        vc   += (gi >= 0);
    }
    sf[tid] = lsum; si[tid] = vc;
    __syncthreads();
    for (int st = 128; st > 0; st >>= 1) {
        if (tid < st) { sf[tid] += sf[tid + st]; si[tid] += si[tid + st]; }
        __syncthreads();
    }

    float ax = 0, ay = 0, bx = 0, by = 0, cx = 0, cy = 0, ex = 0, ey = 0;
    int t = 0;
    const int len4 = (len < 1024 ? len : 1024) & ~3;
    for (; t < len4; t += 4) {
        int p0 = sp[t], p1 = sp[t + 1], p2 = sp[t + 2], p3 = sp[t + 3];
        uint32_t u0 = reinterpret_cast<const uint32_t*>(d_featsbf + (size_t)p0 * NC)[tid];
        uint32_t u1 = reinterpret_cast<const uint32_t*>(d_featsbf + (size_t)p1 * NC)[tid];
        uint32_t u2 = reinterpret_cast<const uint32_t*>(d_featsbf + (size_t)p2 * NC)[tid];
        uint32_t u3 = reinterpret_cast<const uint32_t*>(d_featsbf + (size_t)p3 * NC)[tid];
        float2 f0 = __bfloat1622float2(*reinterpret_cast<__nv_bfloat162*>(&u0));
        float2 f1 = __bfloat1622float2(*reinterpret_cast<__nv_bfloat162*>(&u1));
        float2 f2 = __bfloat1622float2(*reinterpret_cast<__nv_bfloat162*>(&u2));
        float2 f3 = __bfloat1622float2(*reinterpret_cast<__nv_bfloat162*>(&u3));
        ax += f0.x; ay += f0.y;
        bx += f1.x; by += f1.y;
        cx += f2.x; cy += f2.y;
        ex += f3.x; ey += f3.y;
    }
    for (; t < len; ++t) {
        int p;
        if (t < 1024) p = sp[t];
        else { int gi = d_ptom[ctpm[start + t]]; p = (gi < 0) ? (NP - 1) : gi; }
        uint32_t u = reinterpret_cast<const uint32_t*>(d_featsbf + (size_t)p * NC)[tid];
        float2 f = __bfloat1622float2(*reinterpret_cast<__nv_bfloat162*>(&u));
        ax += f.x; ay += f.y;
    }
    reinterpret_cast<float2*>(d_g + (size_t)n * NC)[tid] =
        make_float2(ax + bx + cx + ex, ay + by + cy + ey);

    if (tid == 0) {
        float realn = (float)si[0];
        d_Lsum[n] = sf[0];
        d_realn[n] = realn;
        size_t base = (size_t)NM * NM;
        if (out_size >= (int)(base + NM))     out[base + n] = realn;
        if (out_size >= (int)(base + 2 * NM)) out[base + NM + n] = (realn > 0.f) ? 1.f : 0.f;
    }
}

// ---------------- final small GEMM: pooled = (s*(g @ E^T) - L)/c  (fp32) ----
__launch_bounds__(256, 2)
__global__ void k_final(const float* __restrict__ E, const float* __restrict__ lscale,
                        float* __restrict__ out) {
    __shared__ __align__(16) float As[16][128];
    __shared__ __align__(16) float Bs[16][128];

    const int tid = threadIdx.x;
    const int r0g = blockIdx.y * 128;
    const int n0  = blockIdx.x * 128;
    const int tr = tid >> 4, tc = tid & 15;

    float acc[8][8];
#pragma unroll
    for (int i = 0; i < 8; i++)
#pragma unroll
        for (int j = 0; j < 8; j++) acc[i][j] = 0.f;

    for (int k0 = 0; k0 < NC; k0 += 16) {
#pragma unroll
        for (int i = 0; i < 2; i++) {
            int li  = tid * 2 + i;
            int row = li >> 2;
            int f4  = li & 3;
            float4 a = *reinterpret_cast<const float4*>(
                d_g + (size_t)(r0g + row) * NC + k0 + f4 * 4);
            As[f4 * 4 + 0][row] = a.x; As[f4 * 4 + 1][row] = a.y;
            As[f4 * 4 + 2][row] = a.z; As[f4 * 4 + 3][row] = a.w;
            float4 b = *reinterpret_cast<const float4*>(
                E + (size_t)(n0 + row) * NC + k0 + f4 * 4);
            Bs[f4 * 4 + 0][row] = b.x; Bs[f4 * 4 + 1][row] = b.y;
            Bs[f4 * 4 + 2][row] = b.z; Bs[f4 * 4 + 3][row] = b.w;
        }
        __syncthreads();
#pragma unroll
        for (int k = 0; k < 16; k++) {
            float4 a0 = *reinterpret_cast<const float4*>(&As[k][tr * 4]);
            float4 a1 = *reinterpret_cast<const float4*>(&As[k][64 + tr * 4]);
            float4 b0 = *reinterpret_cast<const float4*>(&Bs[k][tc * 4]);
            float4 b1 = *reinterpret_cast<const float4*>(&Bs[k][64 + tc * 4]);
            float ar[8] = {a0.x, a0.y, a0.z, a0.w, a1.x, a1.y, a1.z, a1.w};
            float br[8] = {b0.x, b0.y, b0.z, b0.w, b1.x, b1.y, b1.z, b1.w};
#pragma unroll
            for (int i = 0; i < 8; i++)
#pragma unroll
                for (int j = 0; j < 8; j++) acc[i][j] = fmaf(ar[i], br[j], acc[i][j]);
        }
        __syncthreads();
    }

    const float s = expf(lscale[0]);
#pragma unroll
    for (int i = 0; i < 8; i++) {
        int ri = (i < 4) ? (tr * 4 + i) : (64 + tr * 4 + (i - 4));
        int n = r0g + ri;
        float c = d_realn[n];
        float invc = (c > 0.f) ? (1.f / c) : 0.f;
        float L = d_Lsum[n];
#pragma unroll
        for (int j = 0; j < 8; j++) {
            int cj = (j < 4) ? (tc * 4 + j) : (64 + tc * 4 + (j - 4));
            int m = n0 + cj;
            out[(size_t)n * NM + m] = (s * acc[i][j] - L) * invc;
        }
    }
}

// ---------------- launch (fork-join: init+scatter overlap the GEMM) ---------
extern "C" void kernel_launch(void* const* d_in, const int* in_sizes, int n_in,
                              void* d_out, int out_size) {
    const float* adapter = (const float*)d_in[0];   // [V, C]
    const float* E       = (const float*)d_in[1];   // [M, C]
    const float* lscale  = (const float*)d_in[2];   // [1]
    const int*   v2p     = (const int*)d_in[3];     // [P]
    const int*   origin  = (const int*)d_in[4];     // [P]
    const int*   ctpm    = (const int*)d_in[5];     // [T]
    const int*   seg     = (const int*)d_in[6];     // [T] sorted
    float* out = (float*)d_out;

    static cudaStream_t s2 = nullptr;
    static cudaEvent_t  ef = nullptr, ej = nullptr;
    if (!s2) {
        cudaStreamCreateWithFlags(&s2, cudaStreamNonBlocking);
        cudaEventCreateWithFlags(&ef, cudaEventDisableTiming);
        cudaEventCreateWithFlags(&ej, cudaEventDisableTiming);
        cudaFuncSetAttribute(k_gemm_lse_mma, cudaFuncAttributeMaxDynamicSharedMemorySize, SMEM_MMA);
    }

    // fork: ptom init + scatter + segment starts on side stream
    cudaEventRecord(ef, 0);
    cudaStreamWaitEvent(s2, ef, 0);
    k_init<<<(NPORIG + 255) / 256, 256, 0, s2>>>(seg);
    k_scatter<<<NP / 256, 256, 0, s2>>>(origin);
    cudaEventRecord(ej, s2);

    // main stream: GEMM path
    k_prepE<<<(NM * NC / 4) / 256, 256>>>(E);
    k_gemm_lse_mma<<<NP / 64, 256, SMEM_MMA>>>(adapter, v2p, lscale);

    // join before segacc (needs ptom + segstart + lse + featsbf)
    cudaStreamWaitEvent(0, ej, 0);
    k_segacc<<<NM, 256>>>(ctpm, out, out_size);
    dim3 g2(NM / 128, NM / 128);
    k_final<<<g2, 256>>>(E, lscale, out);
}

// round 17
// speedup vs baseline: 1.3233x; 1.1272x over previous
#include <cuda_runtime.h>
#include <cuda_bf16.h>
#include <math.h>
#include <cstdint>

#define NV      81920
#define NP      131072
#define NC      512
#define NM      1024
#define NPORIG  163840
#define NT      262144

// ---------------- scratch (static device globals; no allocations) -----------
__device__ __align__(16) __nv_bfloat16  d_featsbf[(size_t)NP * NC];  // bf16 normalized feats
__device__ __align__(16) __nv_bfloat16  d_Ebf[(size_t)NM * NC];      // bf16 caption embeds
__device__ float d_lse[NP];
__device__ int   d_ptom[NPORIG];
__device__ int   d_segstart[NM + 1];
__device__ __align__(16) float d_g[(size_t)NM * NC];
__device__ float d_Lsum[NM];
__device__ float d_realn[NM];

// ---------------- helpers (arch-agnostic: ldmatrix + mma.sync + cp.async) ---
__device__ __forceinline__ uint32_t smem_u32(const void* p) {
    uint32_t a;
    asm("{ .reg .u64 t; cvta.to.shared.u64 t, %1; cvt.u32.u64 %0, t; }" : "=r"(a) : "l"(p));
    return a;
}
__device__ __forceinline__ void ldsm4(uint32_t* r, uint32_t addr) {
    asm volatile("ldmatrix.sync.aligned.m8n8.x4.shared.b16 {%0,%1,%2,%3}, [%4];"
                 : "=r"(r[0]), "=r"(r[1]), "=r"(r[2]), "=r"(r[3]) : "r"(addr));
}
__device__ __forceinline__ void mma16816(float* d, const uint32_t* a, uint32_t b0, uint32_t b1) {
    asm volatile("mma.sync.aligned.m16n8k16.row.col.f32.bf16.bf16.f32 "
                 "{%0,%1,%2,%3}, {%4,%5,%6,%7}, {%8,%9}, {%0,%1,%2,%3};"
                 : "+f"(d[0]), "+f"(d[1]), "+f"(d[2]), "+f"(d[3])
                 : "r"(a[0]), "r"(a[1]), "r"(a[2]), "r"(a[3]), "r"(b0), "r"(b1));
}
__device__ __forceinline__ void cp16(uint32_t dst, const void* src) {
    asm volatile("cp.async.cg.shared.global [%0], [%1], 16;" :: "r"(dst), "l"(src));
}
__device__ __forceinline__ void cp_commit() { asm volatile("cp.async.commit_group;"); }
__device__ __forceinline__ void cp_wait0()  { asm volatile("cp.async.wait_group 0;"); }

__device__ __forceinline__ int lb(const int* a, int n, int key) {
    int lo = 0, hi = n;
    while (lo < hi) { int mid = (lo + hi) >> 1; if (a[mid] < key) lo = mid + 1; else hi = mid; }
    return lo;
}

// ---------------- init (side stream): ptom = -1 + segment starts ------------
__global__ void k_init(const int* __restrict__ seg) {
    int i = blockIdx.x * blockDim.x + threadIdx.x;
    if (i < NPORIG) d_ptom[i] = -1;
    if (i <= NM)    d_segstart[i] = lb(seg, NT, i);
}

// ptom[origin_idx[i]] = i, duplicates: largest i wins (XLA sequential scatter)
__global__ void k_scatter(const int* __restrict__ origin) {
    int i = blockIdx.x * blockDim.x + threadIdx.x;
    if (i < NP) atomicMax(&d_ptom[origin[i]], i);
}

// E -> bf16 (main stream; GEMM input, stays L2-resident)
__global__ void k_prepE(const float* __restrict__ E) {
    int idx = blockIdx.x * blockDim.x + threadIdx.x;   // < NM*NC/4
    float4 v = reinterpret_cast<const float4*>(E)[idx];
    __nv_bfloat162 h0 = __float22bfloat162_rn(make_float2(v.x, v.y));
    __nv_bfloat162 h1 = __float22bfloat162_rn(make_float2(v.z, v.w));
    uint2 u;
    u.x = *reinterpret_cast<uint32_t*>(&h0);
    u.y = *reinterpret_cast<uint32_t*>(&h1);
    reinterpret_cast<uint2*>(d_Ebf)[idx] = u;
}

// ---------------- shared GEMM geometry --------------------------------------
#define A_STRIDE 520
#define A_BYTES  (64 * A_STRIDE * 2)     // 66560
#define KC       64
#define B_STRIDE 72
#define B_BYTES  (128 * B_STRIDE * 2)    // 18432
#define SMEM_MMA (A_BYTES + 2 * B_BYTES) // 103424

__device__ __forceinline__ void issue_B(uint32_t sB, int buf, int nc, int kc, int tid) {
    const __nv_bfloat16* bsrc = d_Ebf + (size_t)(nc * 128) * NC + kc * KC;
    uint32_t dbase = sB + buf * B_BYTES;
#pragma unroll
    for (int i = 0; i < 4; i++) {
        int idx = tid + i * 256;            // 1024 x 16B
        int row = idx >> 3, seg = idx & 7;
        cp16(dbase + (row * B_STRIDE + seg * 8) * 2, bsrc + (size_t)row * NC + seg * 8);
    }
}

// ---------------- fused norm + lse GEMM: 64 rows x 1024 caps x 512 per CTA --
// (R11 kernel verbatim: 256 threads, 2x4 warp grid of 32x32, 2 CTAs/SM)
__global__ void __launch_bounds__(256, 2)
k_gemm_lse_mma(const float* __restrict__ adapter, const int* __restrict__ v2p,
               const float* __restrict__ lscale) {
    extern __shared__ char smem[];
    __shared__ float srow[64];
    const uint32_t sA = smem_u32(smem);
    const uint32_t sB = sA + A_BYTES;
    const int tid = threadIdx.x, lane = tid & 31, wid = tid >> 5;
    const int warp_m = wid & 1, warp_n = wid >> 1;   // 2x4 warp grid, 32x32 each
    const int p0 = blockIdx.x * 64;

    if (tid < 64) srow[tid] = 0.f;

    // B(0,0) in flight while we do the fused norm prolog
    issue_B(sB, 0, 0, 0, tid);
    cp_commit();

    // fused gather + L2-normalize: warp per point, 8 points per warp
    for (int r = wid; r < 64; r += 8) {
        const int p = p0 + r;
        const float4* src = reinterpret_cast<const float4*>(adapter + (size_t)v2p[p] * NC);
        float4 v[4];
        float ss = 0.f;
#pragma unroll
        for (int i = 0; i < 4; i++) {
            v[i] = src[lane + 32 * i];
            ss += v[i].x * v[i].x + v[i].y * v[i].y + v[i].z * v[i].z + v[i].w * v[i].w;
        }
#pragma unroll
        for (int o = 16; o > 0; o >>= 1) ss += __shfl_xor_sync(0xffffffffu, ss, o);
        float scale = 1.f / fmaxf(sqrtf(ss), 1e-12f);
        uint2* gdst = reinterpret_cast<uint2*>(d_featsbf + (size_t)p * NC);
        char*  sdst = smem + r * (A_STRIDE * 2);
#pragma unroll
        for (int i = 0; i < 4; i++) {
            float4 w = v[i];
            w.x *= scale; w.y *= scale; w.z *= scale; w.w *= scale;
            __nv_bfloat162 h0 = __float22bfloat162_rn(make_float2(w.x, w.y));
            __nv_bfloat162 h1 = __float22bfloat162_rn(make_float2(w.z, w.w));
            uint2 u;
            u.x = *reinterpret_cast<uint32_t*>(&h0);
            u.y = *reinterpret_cast<uint32_t*>(&h1);
            gdst[lane + 32 * i] = u;                                  // for k_segacc
            *reinterpret_cast<uint2*>(sdst + (lane + 32 * i) * 8) = u; // smem A
        }
    }
    __syncthreads();   // A tile ready for all warps

    const float s = expf(lscale[0]);

    // ldmatrix per-lane byte offsets
    const uint32_t aoff = ((warp_m * 32 + (lane & 15)) * A_STRIDE + ((lane >> 4) << 3)) * 2;
    const uint32_t boff = ((warp_n * 32 + (lane & 7) + ((lane >> 4) << 3)) * B_STRIDE
                          + ((lane >> 3) & 1) * 8) * 2;

    float t[4] = {0.f, 0.f, 0.f, 0.f};   // per-thread row exp-sums (rows fixed across nc)

    for (int nc = 0; nc < 8; nc++) {
        float acc[2][4][4];
#pragma unroll
        for (int i = 0; i < 2; i++)
#pragma unroll
            for (int j = 0; j < 4; j++)
#pragma unroll
                for (int k = 0; k < 4; k++) acc[i][j][k] = 0.f;

        for (int kc = 0; kc < 8; kc++) {
            cp_wait0();
            __syncthreads();   // stage (nc,kc) visible; prior buffer reads done
            // prefetch next stage into the other buffer (overlaps compute below)
            if (kc < 7)        { issue_B(sB, (kc + 1) & 1, nc, kc + 1, tid); cp_commit(); }
            else if (nc < 7)   { issue_B(sB, 0, nc + 1, 0, tid);             cp_commit(); }

            const uint32_t abase = sA + aoff + kc * (KC * 2);
            const uint32_t bbase = sB + (kc & 1) * B_BYTES + boff;
#pragma unroll
            for (int kk = 0; kk < 4; kk++) {
                uint32_t a0[4], a1[4];
                ldsm4(a0, abase + kk * 32);
                ldsm4(a1, abase + kk * 32 + 16 * A_STRIDE * 2);
#pragma unroll
                for (int np = 0; np < 2; np++) {
                    uint32_t b[4];
                    ldsm4(b, bbase + kk * 32 + np * 16 * B_STRIDE * 2);
                    mma16816(acc[0][2 * np],     a0, b[0], b[1]);
                    mma16816(acc[0][2 * np + 1], a0, b[2], b[3]);
                    mma16816(acc[1][2 * np],     a1, b[0], b[1]);
                    mma16816(acc[1][2 * np + 1], a1, b[2], b[3]);
                }
            }
        }
        // epilogue: exp-sum this 128-caption chunk into register totals
#pragma unroll
        for (int mt = 0; mt < 2; mt++)
#pragma unroll
            for (int nt = 0; nt < 4; nt++) {
                t[mt * 2 + 0] += __expf(s * acc[mt][nt][0]) + __expf(s * acc[mt][nt][1]);
                t[mt * 2 + 1] += __expf(s * acc[mt][nt][2]) + __expf(s * acc[mt][nt][3]);
            }
    }

    // reduce across the 4 lanes sharing each row, then across warp_n via smem
#pragma unroll
    for (int i = 0; i < 4; i++) {
        t[i] += __shfl_xor_sync(0xffffffffu, t[i], 1);
        t[i] += __shfl_xor_sync(0xffffffffu, t[i], 2);
    }
    if ((lane & 3) == 0) {
#pragma unroll
        for (int i = 0; i < 4; i++) {
            int r = warp_m * 32 + (i >> 1) * 16 + (i & 1) * 8 + (lane >> 2);
            atomicAdd(&srow[r], t[i]);
        }
    }
    __syncthreads();
    if (tid < 64) d_lse[p0 + tid] = logf(srow[tid]);
}

// ---------------- per-caption segmented accumulation (seg_idx is sorted) ----
__global__ void k_segacc(const int* __restrict__ ctpm,
                         float* __restrict__ out, int out_size) {
    const int n = blockIdx.x;
    const int tid = threadIdx.x;  // 256: thread owns cols 2*tid, 2*tid+1
    const int start = d_segstart[n];
    const int len   = d_segstart[n + 1] - start;

    __shared__ int   sp[1024];
    __shared__ float sf[256];
    __shared__ int   si[256];

    float lsum = 0.f; int vc = 0;
    for (int i = tid; i < len; i += 256) {
        int gi = d_ptom[ctpm[start + i]];
        int p = (gi < 0) ? (NP - 1) : gi;   // torch negative-index wrap
        if (i < 1024) sp[i] = p;
        lsum += d_lse[p];
        vc   += (gi >= 0);
    }
    sf[tid] = lsum; si[tid] = vc;
    __syncthreads();
    for (int st = 128; st > 0; st >>= 1) {
        if (tid < st) { sf[tid] += sf[tid + st]; si[tid] += si[tid + st]; }
        __syncthreads();
    }

    float ax = 0, ay = 0, bx = 0, by = 0, cx = 0, cy = 0, ex = 0, ey = 0;
    int t = 0;
    const int len4 = (len < 1024 ? len : 1024) & ~3;
    for (; t < len4; t += 4) {
        int p0 = sp[t], p1 = sp[t + 1], p2 = sp[t + 2], p3 = sp[t + 3];
        uint32_t u0 = reinterpret_cast<const uint32_t*>(d_featsbf + (size_t)p0 * NC)[tid];
        uint32_t u1 = reinterpret_cast<const uint32_t*>(d_featsbf + (size_t)p1 * NC)[tid];
        uint32_t u2 = reinterpret_cast<const uint32_t*>(d_featsbf + (size_t)p2 * NC)[tid];
        uint32_t u3 = reinterpret_cast<const uint32_t*>(d_featsbf + (size_t)p3 * NC)[tid];
        float2 f0 = __bfloat1622float2(*reinterpret_cast<__nv_bfloat162*>(&u0));
        float2 f1 = __bfloat1622float2(*reinterpret_cast<__nv_bfloat162*>(&u1));
        float2 f2 = __bfloat1622float2(*reinterpret_cast<__nv_bfloat162*>(&u2));
        float2 f3 = __bfloat1622float2(*reinterpret_cast<__nv_bfloat162*>(&u3));
        ax += f0.x; ay += f0.y;
        bx += f1.x; by += f1.y;
        cx += f2.x; cy += f2.y;
        ex += f3.x; ey += f3.y;
    }
    for (; t < len; ++t) {
        int p;
        if (t < 1024) p = sp[t];
        else { int gi = d_ptom[ctpm[start + t]]; p = (gi < 0) ? (NP - 1) : gi; }
        uint32_t u = reinterpret_cast<const uint32_t*>(d_featsbf + (size_t)p * NC)[tid];
        float2 f = __bfloat1622float2(*reinterpret_cast<__nv_bfloat162*>(&u));
        ax += f.x; ay += f.y;
    }
    reinterpret_cast<float2*>(d_g + (size_t)n * NC)[tid] =
        make_float2(ax + bx + cx + ex, ay + by + cy + ey);

    if (tid == 0) {
        float realn = (float)si[0];
        d_Lsum[n] = sf[0];
        d_realn[n] = realn;
        size_t base = (size_t)NM * NM;
        if (out_size >= (int)(base + NM))     out[base + n] = realn;
        if (out_size >= (int)(base + 2 * NM)) out[base + NM + n] = (realn > 0.f) ? 1.f : 0.f;
    }
}

// ---------------- final GEMM via HMMA: pooled = (s*(g @ E^T) - L)/c ---------
// CTA = 64 g-rows x 128 cols, grid (16,8) = 128 CTAs; same warp layout and
// B pipeline as the lse GEMM; A converted fp32 -> bf16 during smem staging.
__global__ void __launch_bounds__(256, 2)
k_final_mma(const float* __restrict__ lscale, float* __restrict__ out) {
    extern __shared__ char smem[];
    const uint32_t sA = smem_u32(smem);
    const uint32_t sB = sA + A_BYTES;
    const int tid = threadIdx.x, lane = tid & 31, wid = tid >> 5;
    const int warp_m = wid & 1, warp_n = wid >> 1;   // 2x4 warp grid, 32x32 each
    const int r0 = blockIdx.x * 64;    // g-row block
    const int n0 = blockIdx.y * 128;   // E-col block

    issue_B(sB, 0, n0 / 128, 0, tid);
    cp_commit();

    // stage A: d_g rows r0..r0+63 fp32 -> bf16 smem (stride 520)
#pragma unroll
    for (int i = 0; i < 32; i++) {
        int li = tid + i * 256;            // 8192 float4
        int row = li >> 7, f4 = li & 127;
        float4 v = *reinterpret_cast<const float4*>(d_g + (size_t)(r0 + row) * NC + f4 * 4);
        __nv_bfloat162 h0 = __float22bfloat162_rn(make_float2(v.x, v.y));
        __nv_bfloat162 h1 = __float22bfloat162_rn(make_float2(v.z, v.w));
        uint2 u;
        u.x = *reinterpret_cast<uint32_t*>(&h0);
        u.y = *reinterpret_cast<uint32_t*>(&h1);
        *reinterpret_cast<uint2*>(smem + (row * A_STRIDE + f4 * 4) * 2) = u;
    }
    __syncthreads();

    const uint32_t aoff = ((warp_m * 32 + (lane & 15)) * A_STRIDE + ((lane >> 4) << 3)) * 2;
    const uint32_t boff = ((warp_n * 32 + (lane & 7) + ((lane >> 4) << 3)) * B_STRIDE
                          + ((lane >> 3) & 1) * 8) * 2;

    float acc[2][4][4];
#pragma unroll
    for (int i = 0; i < 2; i++)
#pragma unroll
        for (int j = 0; j < 4; j++)
#pragma unroll
            for (int k = 0; k < 4; k++) acc[i][j][k] = 0.f;

    for (int kc = 0; kc < 8; kc++) {
        cp_wait0();
        __syncthreads();
        if (kc < 7) { issue_B(sB, (kc + 1) & 1, n0 / 128, kc + 1, tid); cp_commit(); }

        const uint32_t abase = sA + aoff + kc * (KC * 2);
        const uint32_t bbase = sB + (kc & 1) * B_BYTES + boff;
#pragma unroll
        for (int kk = 0; kk < 4; kk++) {
            uint32_t a0[4], a1[4];
            ldsm4(a0, abase + kk * 32);
            ldsm4(a1, abase + kk * 32 + 16 * A_STRIDE * 2);
#pragma unroll
            for (int np = 0; np < 2; np++) {
                uint32_t b[4];
                ldsm4(b, bbase + kk * 32 + np * 16 * B_STRIDE * 2);
                mma16816(acc[0][2 * np],     a0, b[0], b[1]);
                mma16816(acc[0][2 * np + 1], a0, b[2], b[3]);
                mma16816(acc[1][2 * np],     a1, b[0], b[1]);
                mma16816(acc[1][2 * np + 1], a1, b[2], b[3]);
            }
        }
    }

    // epilogue: (s*acc - L) * invc, fragment mapping row = mt*16 + h*8 + lane>>2
    const float s = expf(lscale[0]);
#pragma unroll
    for (int mt = 0; mt < 2; mt++)
#pragma unroll
        for (int h = 0; h < 2; h++) {
            int row = r0 + warp_m * 32 + mt * 16 + h * 8 + (lane >> 2);
            float c = d_realn[row];
            float invc = (c > 0.f) ? (1.f / c) : 0.f;
            float L = d_Lsum[row];
#pragma unroll
            for (int nt = 0; nt < 4; nt++) {
                int col = n0 + warp_n * 32 + (nt >> 1) * 16 + (nt & 1) * 8 + (lane & 3) * 2;
                out[(size_t)row * NM + col]     = (s * acc[mt][nt][2 * h]     - L) * invc;
                out[(size_t)row * NM + col + 1] = (s * acc[mt][nt][2 * h + 1] - L) * invc;
            }
        }
}

// ---------------- launch (fork-join: init+scatter overlap the GEMM) ---------
extern "C" void kernel_launch(void* const* d_in, const int* in_sizes, int n_in,
                              void* d_out, int out_size) {
    const float* adapter = (const float*)d_in[0];   // [V, C]
    const float* E       = (const float*)d_in[1];   // [M, C]
    const float* lscale  = (const float*)d_in[2];   // [1]
    const int*   v2p     = (const int*)d_in[3];     // [P]
    const int*   origin  = (const int*)d_in[4];     // [P]
    const int*   ctpm    = (const int*)d_in[5];     // [T]
    const int*   seg     = (const int*)d_in[6];     // [T] sorted
    float* out = (float*)d_out;

    static cudaStream_t s2 = nullptr;
    static cudaEvent_t  ef = nullptr, ej = nullptr;
    if (!s2) {
        cudaStreamCreateWithFlags(&s2, cudaStreamNonBlocking);
        cudaEventCreateWithFlags(&ef, cudaEventDisableTiming);
        cudaEventCreateWithFlags(&ej, cudaEventDisableTiming);
        cudaFuncSetAttribute(k_gemm_lse_mma, cudaFuncAttributeMaxDynamicSharedMemorySize, SMEM_MMA);
        cudaFuncSetAttribute(k_final_mma,    cudaFuncAttributeMaxDynamicSharedMemorySize, SMEM_MMA);
    }

    // fork: ptom init + scatter + segment starts on side stream
    cudaEventRecord(ef, 0);
    cudaStreamWaitEvent(s2, ef, 0);
    k_init<<<(NPORIG + 255) / 256, 256, 0, s2>>>(seg);
    k_scatter<<<NP / 256, 256, 0, s2>>>(origin);
    cudaEventRecord(ej, s2);

    // main stream: GEMM path
    k_prepE<<<(NM * NC / 4) / 256, 256>>>(E);
    k_gemm_lse_mma<<<NP / 64, 256, SMEM_MMA>>>(adapter, v2p, lscale);

    // join before segacc (needs ptom + segstart + lse + featsbf)
    cudaStreamWaitEvent(0, ej, 0);
    k_segacc<<<NM, 256>>>(ctpm, out, out_size);
    dim3 gf(16, 8);
    k_final_mma<<<gf, 256, SMEM_MMA>>>(lscale, out);
}